// round 2
// baseline (speedup 1.0000x reference)
#include <cuda_runtime.h>
#include <cuda_bf16.h>
#include <cstdint>

#define N_NODES 50000
#define N_EDGES 800000
#define F 64
#define C 16

// ---------------- device scratch (no allocations allowed) ----------------
// NOTE: these are referenced ONLY from device code (never passed as kernel
// args from host — host-side symbol decay gives the host shadow address,
// which ATS on GB300 happily lets the GPU write, silently corrupting nothing
// useful; that was the R1 bug).
__device__ __align__(256) float g_sum1[N_NODES * F];
__device__ __align__(256) float g_sum2[N_NODES * F];
__device__ __align__(256) float g_h1  [N_NODES * F];
__device__ __align__(256) float g_deg [N_NODES];
__device__ int g_src32[N_EDGES];
__device__ int g_dst32[N_EDGES];
__device__ int g_is64;

// ---------------- index layout detection + normalization ----------------
// Reference declares int64 indices; JAX may demote to int32. Indices are in
// [0, 50000), so if data is little-endian int64 every odd 32-bit word is 0.
__global__ void detect_kernel(const unsigned int* __restrict__ raw_src) {
    __shared__ int any_nonzero;
    if (threadIdx.x == 0) any_nonzero = 0;
    __syncthreads();
    for (int i = threadIdx.x; i < 1024; i += blockDim.x) {
        if (raw_src[2 * i + 1] != 0u) any_nonzero = 1;
    }
    __syncthreads();
    if (threadIdx.x == 0) g_is64 = (any_nonzero == 0) ? 1 : 0;
}

__global__ void convert_kernel(const int* __restrict__ raw_src,
                               const int* __restrict__ raw_dst) {
    int e = blockIdx.x * blockDim.x + threadIdx.x;
    if (e >= N_EDGES) return;
    int idx = g_is64 ? (2 * e) : e;
    g_src32[e] = raw_src[idx];
    g_dst32[e] = raw_dst[idx];
}

// ---------------- zero scratch ----------------
__global__ void zero_kernel() {
    int i = blockIdx.x * blockDim.x + threadIdx.x;
    int stride = gridDim.x * blockDim.x;
    for (int j = i; j < N_NODES * F; j += stride) {
        g_sum1[j] = 0.0f;
        g_sum2[j] = 0.0f;
    }
    for (int j = i; j < N_NODES; j += stride) g_deg[j] = 0.0f;
}

// ---------------- edge scatter: sum[dst] += feat[src], 16 lanes/edge ----
__device__ __forceinline__ void red_add_v4(float* p, float4 v) {
    asm volatile(
        "{ .reg .u64 pg; cvta.to.global.u64 pg, %0;\n"
        "  red.global.add.v4.f32 [pg], {%1, %2, %3, %4}; }"
        :: "l"(p), "f"(v.x), "f"(v.y), "f"(v.z), "f"(v.w)
        : "memory");
}

// LAYER=1: feat = x (param), accumulate into g_sum1, count g_deg.
// LAYER=2: feat = g_h1 (device symbol), accumulate into g_sum2.
template <int LAYER>
__global__ void scatter_kernel(const float* __restrict__ x_in) {
    long long gid = (long long)blockIdx.x * blockDim.x + threadIdx.x;
    int e = (int)(gid >> 4);
    int l = (int)(gid & 15);
    if (e >= N_EDGES) return;
    int s = g_src32[e];
    int d = g_dst32[e];
    const float* feat = (LAYER == 1) ? x_in : g_h1;
    float*       sum  = (LAYER == 1) ? g_sum1 : g_sum2;
    float4 v = *(const float4*)(feat + (size_t)s * F + l * 4);
    red_add_v4(sum + (size_t)d * F + l * 4, v);
    if (LAYER == 1 && l == 0) atomicAdd(&g_deg[d], 1.0f);
}

// ---------------- layer 1: h1 = relu(x@Ws + (sum1/deg)@Wn + b) ----------
// 512 threads = 8 nodes x 64 output cols.
__global__ void layer1_kernel(const float* __restrict__ x,
                              const float* __restrict__ Ws,
                              const float* __restrict__ Wn,
                              const float* __restrict__ b) {
    __shared__ float sWs[64][64];
    __shared__ float sWn[64][64];
    __shared__ float sx[8][64];
    __shared__ float sa[8][64];
    int tid = threadIdx.x;
    for (int i = tid; i < 64 * 64; i += 512) {
        sWs[i >> 6][i & 63] = Ws[i];
        sWn[i >> 6][i & 63] = Wn[i];
    }
    int node0 = blockIdx.x * 8;
    for (int i = tid; i < 8 * 64; i += 512) {
        int n = i >> 6, f = i & 63;
        int node = node0 + n;
        if (node < N_NODES) {
            sx[n][f] = x[(size_t)node * F + f];
            float dg = fmaxf(g_deg[node], 1.0f);
            sa[n][f] = g_sum1[(size_t)node * F + f] / dg;
        }
    }
    __syncthreads();
    int n = tid >> 6, col = tid & 63;
    int node = node0 + n;
    if (node >= N_NODES) return;
    float acc = b[col];
#pragma unroll
    for (int k = 0; k < 64; k++) {
        acc += sx[n][k] * sWs[k][col] + sa[n][k] * sWn[k][col];
    }
    g_h1[(size_t)node * F + col] = fmaxf(acc, 0.0f);
}

// ---------------- layer 2: out = h1@Ws + (sum2/deg)@Wn + b --------------
// 512 threads = 32 nodes x 16 output cols.
__global__ void layer2_kernel(const float* __restrict__ Ws,
                              const float* __restrict__ Wn,
                              const float* __restrict__ b,
                              float* __restrict__ out) {
    __shared__ float sWs[64][16];
    __shared__ float sWn[64][16];
    __shared__ float sh[32][64];
    __shared__ float sa[32][64];
    int tid = threadIdx.x;
    for (int i = tid; i < 64 * 16; i += 512) {
        sWs[i >> 4][i & 15] = Ws[i];
        sWn[i >> 4][i & 15] = Wn[i];
    }
    int node0 = blockIdx.x * 32;
    for (int i = tid; i < 32 * 64; i += 512) {
        int n = i >> 6, f = i & 63;
        int node = node0 + n;
        if (node < N_NODES) {
            sh[n][f] = g_h1[(size_t)node * F + f];
            float dg = fmaxf(g_deg[node], 1.0f);
            sa[n][f] = g_sum2[(size_t)node * F + f] / dg;
        }
    }
    __syncthreads();
    int n = tid >> 4, col = tid & 15;
    int node = node0 + n;
    if (node >= N_NODES) return;
    float acc = b[col];
#pragma unroll
    for (int k = 0; k < 64; k++) {
        acc += sh[n][k] * sWs[k][col] + sa[n][k] * sWn[k][col];
    }
    out[(size_t)node * C + col] = acc;
}

// ---------------- launch ----------------
extern "C" void kernel_launch(void* const* d_in, const int* in_sizes, int n_in,
                              void* d_out, int out_size) {
    const float* x   = (const float*)d_in[0];
    const int*   src = (const int*)d_in[1];   // raw words; layout detected on device
    const int*   dst = (const int*)d_in[2];
    const float* Ws1 = (const float*)d_in[3];
    const float* Wn1 = (const float*)d_in[4];
    const float* b1  = (const float*)d_in[5];
    const float* Ws2 = (const float*)d_in[6];
    const float* Wn2 = (const float*)d_in[7];
    const float* b2  = (const float*)d_in[8];
    float* out = (float*)d_out;

    detect_kernel<<<1, 256>>>((const unsigned int*)src);
    convert_kernel<<<(N_EDGES + 255) / 256, 256>>>(src, dst);
    zero_kernel<<<4096, 256>>>();

    long long total = (long long)N_EDGES * 16;
    int sblocks = (int)((total + 255) / 256);

    scatter_kernel<1><<<sblocks, 256>>>(x);
    layer1_kernel<<<(N_NODES + 7) / 8, 512>>>(x, Ws1, Wn1, b1);

    scatter_kernel<2><<<sblocks, 256>>>(nullptr);
    layer2_kernel<<<(N_NODES + 31) / 32, 512>>>(Ws2, Wn2, b2, out);
}

// round 3
// speedup vs baseline: 1.2841x; 1.2841x over previous
#include <cuda_runtime.h>
#include <cuda_bf16.h>
#include <cstdint>

#define N_NODES 50000
#define N_EDGES 800000
#define F 64
#define C 16
#define SCAN_B 256
#define N_BLK1 ((N_NODES + SCAN_B - 1) / SCAN_B)   // 196

// ---------------- device scratch (device-code references only!) ----------
__device__ __align__(256) float g_h1  [N_NODES * F];   // layer-1 activations
__device__ __align__(256) float g_p2  [N_NODES * C];   // h1 @ Wn2 (pre-projected)
__device__ __align__(256) float g_agg1[N_NODES * F];   // mean_agg(x)
__device__ __align__(256) float g_agg2[N_NODES * C];   // mean_agg(p2)
__device__ int g_src32[N_EDGES];
__device__ int g_dst32[N_EDGES];
__device__ int g_csr_src[N_EDGES];                     // src ids grouped by dst
__device__ int g_cnt[N_NODES];
__device__ int g_off[N_NODES + 1];
__device__ int g_cursor[N_NODES];
__device__ int g_bsum[N_BLK1];
__device__ int g_bpre[N_BLK1];
__device__ int g_is64;

// ---------------- index layout detection ----------------
__global__ void detect_kernel(const unsigned int* __restrict__ raw_src) {
    __shared__ int any_nonzero;
    if (threadIdx.x == 0) any_nonzero = 0;
    __syncthreads();
    for (int i = threadIdx.x; i < 1024; i += blockDim.x)
        if (raw_src[2 * i + 1] != 0u) any_nonzero = 1;
    __syncthreads();
    if (threadIdx.x == 0) g_is64 = (any_nonzero == 0) ? 1 : 0;
}

__global__ void zero_cnt_kernel() {
    int i = blockIdx.x * blockDim.x + threadIdx.x;
    if (i < N_NODES) g_cnt[i] = 0;
}

// convert indices + histogram dst
__global__ void convert_hist_kernel(const int* __restrict__ raw_src,
                                    const int* __restrict__ raw_dst) {
    int e = blockIdx.x * blockDim.x + threadIdx.x;
    if (e >= N_EDGES) return;
    int idx = g_is64 ? (2 * e) : e;
    int s = raw_src[idx];
    int d = raw_dst[idx];
    g_src32[e] = s;
    g_dst32[e] = d;
    atomicAdd(&g_cnt[d], 1);
}

// ---------------- 2-level exclusive scan of g_cnt -> g_off ----------------
__global__ void scan1_kernel() {
    __shared__ int sh[SCAN_B];
    int t = threadIdx.x;
    int idx = blockIdx.x * SCAN_B + t;
    int v = (idx < N_NODES) ? g_cnt[idx] : 0;
    sh[t] = v;
    __syncthreads();
#pragma unroll
    for (int d = 1; d < SCAN_B; d <<= 1) {
        int a = (t >= d) ? sh[t - d] : 0;
        __syncthreads();
        sh[t] += a;
        __syncthreads();
    }
    if (idx < N_NODES) g_off[idx] = sh[t] - v;   // exclusive within block
    if (t == SCAN_B - 1) g_bsum[blockIdx.x] = sh[t];
}

__global__ void scan2_kernel() {
    __shared__ int sh[SCAN_B];
    int t = threadIdx.x;
    int v = (t < N_BLK1) ? g_bsum[t] : 0;
    sh[t] = v;
    __syncthreads();
#pragma unroll
    for (int d = 1; d < SCAN_B; d <<= 1) {
        int a = (t >= d) ? sh[t - d] : 0;
        __syncthreads();
        sh[t] += a;
        __syncthreads();
    }
    if (t < N_BLK1) g_bpre[t] = sh[t] - v;
}

__global__ void scan3_kernel() {
    int idx = blockIdx.x * SCAN_B + threadIdx.x;
    if (idx < N_NODES) {
        int o = g_off[idx] + g_bpre[blockIdx.x];
        g_off[idx] = o;
        g_cursor[idx] = o;
    }
    if (idx == 0) g_off[N_NODES] = N_EDGES;
}

__global__ void fill_kernel() {
    int e = blockIdx.x * blockDim.x + threadIdx.x;
    if (e >= N_EDGES) return;
    int d = g_dst32[e];
    int pos = atomicAdd(&g_cursor[d], 1);
    g_csr_src[pos] = g_src32[e];
}

// ---------------- gather1: g_agg1[n] = mean over neighbors of x[src] -----
// 16 lanes per node (64 floats = 16 x float4); 256 thr = 16 nodes/block.
__global__ void gather1_kernel(const float* __restrict__ x) {
    int node = blockIdx.x * 16 + (threadIdx.x >> 4);
    int l = threadIdx.x & 15;
    if (node >= N_NODES) return;
    int beg = g_off[node], end = g_off[node + 1];
    float4 acc = make_float4(0.f, 0.f, 0.f, 0.f);
    int i = beg;
    for (; i + 1 < end; i += 2) {
        int s0 = g_csr_src[i];
        int s1 = g_csr_src[i + 1];
        float4 a = *(const float4*)(x + (size_t)s0 * F + l * 4);
        float4 b = *(const float4*)(x + (size_t)s1 * F + l * 4);
        acc.x += a.x + b.x; acc.y += a.y + b.y;
        acc.z += a.z + b.z; acc.w += a.w + b.w;
    }
    if (i < end) {
        int s0 = g_csr_src[i];
        float4 a = *(const float4*)(x + (size_t)s0 * F + l * 4);
        acc.x += a.x; acc.y += a.y; acc.z += a.z; acc.w += a.w;
    }
    float inv = 1.0f / (float)max(end - beg, 1);
    acc.x *= inv; acc.y *= inv; acc.z *= inv; acc.w *= inv;
    *(float4*)(g_agg1 + (size_t)node * F + l * 4) = acc;
}

// ---------------- gather2: g_agg2[n] = mean over neighbors of p2[src] ----
// 4 lanes per node (16 floats = 4 x float4); 256 thr = 64 nodes/block.
__global__ void gather2_kernel() {
    int node = blockIdx.x * 64 + (threadIdx.x >> 2);
    int l = threadIdx.x & 3;
    if (node >= N_NODES) return;
    int beg = g_off[node], end = g_off[node + 1];
    float4 acc = make_float4(0.f, 0.f, 0.f, 0.f);
    int i = beg;
    for (; i + 1 < end; i += 2) {
        int s0 = g_csr_src[i];
        int s1 = g_csr_src[i + 1];
        float4 a = *(const float4*)(g_p2 + (size_t)s0 * C + l * 4);
        float4 b = *(const float4*)(g_p2 + (size_t)s1 * C + l * 4);
        acc.x += a.x + b.x; acc.y += a.y + b.y;
        acc.z += a.z + b.z; acc.w += a.w + b.w;
    }
    if (i < end) {
        int s0 = g_csr_src[i];
        float4 a = *(const float4*)(g_p2 + (size_t)s0 * C + l * 4);
        acc.x += a.x; acc.y += a.y; acc.z += a.z; acc.w += a.w;
    }
    float inv = 1.0f / (float)max(end - beg, 1);
    acc.x *= inv; acc.y *= inv; acc.z *= inv; acc.w *= inv;
    *(float4*)(g_agg2 + (size_t)node * C + l * 4) = acc;
}

// ---------------- layer 1 fused: h1 = relu(x@Ws1 + agg1@Wn1 + b1);
//                  p2 = h1 @ Wn2.  512 thr = 8 nodes x 64 cols. ------------
__global__ void layer1_kernel(const float* __restrict__ x,
                              const float* __restrict__ Ws,
                              const float* __restrict__ Wn,
                              const float* __restrict__ b,
                              const float* __restrict__ Wn2) {
    __shared__ float sWs[64][64];
    __shared__ float sWn[64][64];
    __shared__ float sW2[64][16];
    __shared__ float sx[8][64];
    __shared__ float sa[8][64];
    __shared__ float sh[8][64];
    int tid = threadIdx.x;
    for (int i = tid; i < 64 * 64; i += 512) {
        sWs[i >> 6][i & 63] = Ws[i];
        sWn[i >> 6][i & 63] = Wn[i];
    }
    for (int i = tid; i < 64 * 16; i += 512)
        sW2[i >> 4][i & 15] = Wn2[i];
    int node0 = blockIdx.x * 8;
    for (int i = tid; i < 8 * 64; i += 512) {
        int n = i >> 6, f = i & 63;
        int node = node0 + n;
        if (node < N_NODES) {
            sx[n][f] = x[(size_t)node * F + f];
            sa[n][f] = g_agg1[(size_t)node * F + f];
        }
    }
    __syncthreads();
    int n = tid >> 6, col = tid & 63;
    int node = node0 + n;
    float h = 0.0f;
    if (node < N_NODES) {
        float acc = b[col];
#pragma unroll
        for (int k = 0; k < 64; k++)
            acc += sx[n][k] * sWs[k][col] + sa[n][k] * sWn[k][col];
        h = fmaxf(acc, 0.0f);
        g_h1[(size_t)node * F + col] = h;
    }
    sh[n][col] = h;
    __syncthreads();
    if (tid < 8 * 16) {
        int nn = tid >> 4, c = tid & 15;
        int nd = node0 + nn;
        if (nd < N_NODES) {
            float acc = 0.0f;
#pragma unroll
            for (int k = 0; k < 64; k++)
                acc += sh[nn][k] * sW2[k][c];
            g_p2[(size_t)nd * C + c] = acc;
        }
    }
}

// ---------------- layer 2: out = h1@Ws2 + agg2 + b2 ----------------------
// 256 thr = 16 nodes x 16 cols.
__global__ void layer2_kernel(const float* __restrict__ Ws,
                              const float* __restrict__ b,
                              float* __restrict__ out) {
    __shared__ float sWs[64][16];
    __shared__ float sh[16][64];
    int tid = threadIdx.x;
    for (int i = tid; i < 64 * 16; i += 256)
        sWs[i >> 4][i & 15] = Ws[i];
    int node0 = blockIdx.x * 16;
    for (int i = tid; i < 16 * 64; i += 256) {
        int n = i >> 6, f = i & 63;
        int node = node0 + n;
        if (node < N_NODES) sh[n][f] = g_h1[(size_t)node * F + f];
    }
    __syncthreads();
    int n = tid >> 4, col = tid & 15;
    int node = node0 + n;
    if (node >= N_NODES) return;
    float acc = b[col] + g_agg2[(size_t)node * C + col];
#pragma unroll
    for (int k = 0; k < 64; k++)
        acc += sh[n][k] * sWs[k][col];
    out[(size_t)node * C + col] = acc;
}

// ---------------- launch ----------------
extern "C" void kernel_launch(void* const* d_in, const int* in_sizes, int n_in,
                              void* d_out, int out_size) {
    const float* x   = (const float*)d_in[0];
    const int*   src = (const int*)d_in[1];
    const int*   dst = (const int*)d_in[2];
    const float* Ws1 = (const float*)d_in[3];
    const float* Wn1 = (const float*)d_in[4];
    const float* b1  = (const float*)d_in[5];
    const float* Ws2 = (const float*)d_in[6];
    const float* Wn2 = (const float*)d_in[7];
    const float* b2  = (const float*)d_in[8];
    float* out = (float*)d_out;

    detect_kernel<<<1, 256>>>((const unsigned int*)src);
    zero_cnt_kernel<<<(N_NODES + 255) / 256, 256>>>();
    convert_hist_kernel<<<(N_EDGES + 255) / 256, 256>>>(src, dst);

    scan1_kernel<<<N_BLK1, SCAN_B>>>();
    scan2_kernel<<<1, SCAN_B>>>();
    scan3_kernel<<<N_BLK1, SCAN_B>>>();
    fill_kernel<<<(N_EDGES + 255) / 256, 256>>>();

    gather1_kernel<<<(N_NODES + 15) / 16, 256>>>(x);
    layer1_kernel<<<(N_NODES + 7) / 8, 512>>>(x, Ws1, Wn1, b1, Wn2);
    gather2_kernel<<<(N_NODES + 63) / 64, 256>>>();
    layer2_kernel<<<(N_NODES + 15) / 16, 256>>>(Ws2, b2, out);
}

// round 4
// speedup vs baseline: 2.1086x; 1.6421x over previous
#include <cuda_runtime.h>
#include <cuda_bf16.h>
#include <cstdint>

#define N_NODES 50000
#define N_EDGES 800000
#define F 64
#define C 16
#define SCAN_B 256
#define N_BLK1 ((N_NODES + SCAN_B - 1) / SCAN_B)   // 196
#define N_TILES ((N_NODES + 63) / 64)              // 782

// ---------------- device scratch (device-code references ONLY) ----------
__device__ __align__(256) float g_agg1[N_NODES * F];   // mean_agg(x)
__device__ __align__(256) float g_p2  [N_NODES * C];   // h1 @ Wn2
__device__ __align__(256) float g_q2  [N_NODES * C];   // h1 @ Ws2
__device__ int g_src32[N_EDGES];
__device__ int g_dst32[N_EDGES];
__device__ int g_csr_src[N_EDGES];
__device__ int g_cnt[N_NODES];
__device__ int g_off[N_NODES + 1];
__device__ int g_cursor[N_NODES];
__device__ int g_bsum[N_BLK1];
__device__ int g_bpre[N_BLK1];
__device__ int g_is64;

// ---------------- packed f32x2 helpers ----------------
__device__ __forceinline__ unsigned long long pack2(float a, float b) {
    unsigned long long r;
    asm("mov.b64 %0, {%1, %2};" : "=l"(r) : "f"(a), "f"(b));
    return r;
}
__device__ __forceinline__ unsigned long long fma2(unsigned long long a,
                                                   unsigned long long b,
                                                   unsigned long long c) {
    unsigned long long d;
    asm("fma.rn.f32x2 %0, %1, %2, %3;" : "=l"(d) : "l"(a), "l"(b), "l"(c));
    return d;
}
__device__ __forceinline__ void unpack2(unsigned long long v, float& lo, float& hi) {
    asm("mov.b64 {%0, %1}, %2;" : "=f"(lo), "=f"(hi) : "l"(v));
}

// ---------------- detect int64-vs-int32 layout + zero counts -------------
__global__ void detect_zero_kernel(const unsigned int* __restrict__ raw_src) {
    int i = blockIdx.x * blockDim.x + threadIdx.x;
    if (i < N_NODES) g_cnt[i] = 0;
    if (blockIdx.x == 0) {
        __shared__ int any_nonzero;
        if (threadIdx.x == 0) any_nonzero = 0;
        __syncthreads();
        for (int j = threadIdx.x; j < 1024; j += blockDim.x)
            if (raw_src[2 * j + 1] != 0u) any_nonzero = 1;
        __syncthreads();
        if (threadIdx.x == 0) g_is64 = (any_nonzero == 0) ? 1 : 0;
    }
}

// convert indices + histogram dst
__global__ void convert_hist_kernel(const int* __restrict__ raw_src,
                                    const int* __restrict__ raw_dst) {
    int e = blockIdx.x * blockDim.x + threadIdx.x;
    if (e >= N_EDGES) return;
    int idx = g_is64 ? (2 * e) : e;
    int s = raw_src[idx];
    int d = raw_dst[idx];
    g_src32[e] = s;
    g_dst32[e] = d;
    atomicAdd(&g_cnt[d], 1);
}

// ---------------- 2-level exclusive scan of g_cnt -> g_off ---------------
__global__ void scan1_kernel() {
    __shared__ int sh[SCAN_B];
    int t = threadIdx.x;
    int idx = blockIdx.x * SCAN_B + t;
    int v = (idx < N_NODES) ? g_cnt[idx] : 0;
    sh[t] = v;
    __syncthreads();
#pragma unroll
    for (int d = 1; d < SCAN_B; d <<= 1) {
        int a = (t >= d) ? sh[t - d] : 0;
        __syncthreads();
        sh[t] += a;
        __syncthreads();
    }
    if (idx < N_NODES) g_off[idx] = sh[t] - v;
    if (t == SCAN_B - 1) g_bsum[blockIdx.x] = sh[t];
}

__global__ void scan2_kernel() {
    __shared__ int sh[SCAN_B];
    int t = threadIdx.x;
    int v = (t < N_BLK1) ? g_bsum[t] : 0;
    sh[t] = v;
    __syncthreads();
#pragma unroll
    for (int d = 1; d < SCAN_B; d <<= 1) {
        int a = (t >= d) ? sh[t - d] : 0;
        __syncthreads();
        sh[t] += a;
        __syncthreads();
    }
    if (t < N_BLK1) g_bpre[t] = sh[t] - v;
}

__global__ void scan3_kernel() {
    int idx = blockIdx.x * SCAN_B + threadIdx.x;
    if (idx < N_NODES) {
        int o = g_off[idx] + g_bpre[blockIdx.x];
        g_off[idx] = o;
        g_cursor[idx] = o;
    }
    if (idx == 0) g_off[N_NODES] = N_EDGES;
}

__global__ void fill_kernel() {
    int e = blockIdx.x * blockDim.x + threadIdx.x;
    if (e >= N_EDGES) return;
    int d = g_dst32[e];
    int pos = atomicAdd(&g_cursor[d], 1);
    g_csr_src[pos] = g_src32[e];
}

// ---------------- gather1: agg1[n] = mean of x[neighbors], MLP=4 --------
// 16 lanes/node (64 floats = 16 float4), 256 thr = 16 nodes/block.
__global__ void gather1_kernel(const float* __restrict__ x) {
    int node = blockIdx.x * 16 + (threadIdx.x >> 4);
    int l = threadIdx.x & 15;
    if (node >= N_NODES) return;
    int beg = g_off[node], end = g_off[node + 1];
    float4 acc = make_float4(0.f, 0.f, 0.f, 0.f);
    int i = beg;
    for (; i + 4 <= end; i += 4) {
        int s0 = g_csr_src[i];
        int s1 = g_csr_src[i + 1];
        int s2 = g_csr_src[i + 2];
        int s3 = g_csr_src[i + 3];
        float4 a = __ldg((const float4*)(x + (size_t)s0 * F + l * 4));
        float4 b = __ldg((const float4*)(x + (size_t)s1 * F + l * 4));
        float4 c = __ldg((const float4*)(x + (size_t)s2 * F + l * 4));
        float4 d = __ldg((const float4*)(x + (size_t)s3 * F + l * 4));
        acc.x += (a.x + b.x) + (c.x + d.x);
        acc.y += (a.y + b.y) + (c.y + d.y);
        acc.z += (a.z + b.z) + (c.z + d.z);
        acc.w += (a.w + b.w) + (c.w + d.w);
    }
    for (; i < end; i++) {
        int s0 = g_csr_src[i];
        float4 a = __ldg((const float4*)(x + (size_t)s0 * F + l * 4));
        acc.x += a.x; acc.y += a.y; acc.z += a.z; acc.w += a.w;
    }
    float inv = 1.0f / (float)max(end - beg, 1);
    acc.x *= inv; acc.y *= inv; acc.z *= inv; acc.w *= inv;
    *(float4*)(g_agg1 + (size_t)node * F + l * 4) = acc;
}

// ---------------- layer1 fused (persistent, f32x2, dynamic smem) --------
// h = relu(x@Ws1 + agg1@Wn1 + b1);  p2 = h@Wn2;  q2 = h@Ws2.
// 256 threads. Thread (ty,tx): 4 nodes x 4 cols register tile.
// Dyn smem: sW[128][64] | sW2[64][32] | sXp[16][68] | sAp[16][68] | sH[64][68]
#define SM_W   0
#define SM_W2  (128 * 64)
#define SM_XP  (SM_W2 + 64 * 32)
#define SM_AP  (SM_XP + 16 * 68)
#define SM_H   (SM_AP + 16 * 68)
#define SM_TOT (SM_H + 64 * 68)          // 16768 floats = 67072 B

__global__ void __launch_bounds__(256, 2)
layer1_kernel(const float* __restrict__ x,
              const float* __restrict__ Ws1,
              const float* __restrict__ Wn1,
              const float* __restrict__ b1,
              const float* __restrict__ Wn2,
              const float* __restrict__ Ws2) {
    extern __shared__ float sm[];
    int tid = threadIdx.x;

    // weights resident in smem for the whole kernel
    for (int i = tid; i < 64 * 64; i += 256) {
        int k = i >> 6, c = i & 63;
        sm[SM_W + k * 64 + c]        = Ws1[i];
        sm[SM_W + (64 + k) * 64 + c] = Wn1[i];
    }
    for (int i = tid; i < 64 * 16; i += 256) {
        int k = i >> 4, c = i & 15;
        sm[SM_W2 + k * 32 + c]      = Wn2[i];
        sm[SM_W2 + k * 32 + 16 + c] = Ws2[i];
    }
    __syncthreads();

    int ty = tid >> 4, tx = tid & 15;              // node group / col group
    float4 bb = *(const float4*)(b1 + tx * 4);

    for (int tile = blockIdx.x; tile < N_TILES; tile += gridDim.x) {
        int node0 = tile * 64;
        unsigned long long acc[4][2];
#pragma unroll
        for (int i = 0; i < 4; i++) { acc[i][0] = 0ull; acc[i][1] = 0ull; }

#pragma unroll
        for (int kp = 0; kp < 4; kp++) {
            __syncthreads();
            {   // load k-panel: 64 nodes x 16 k, transposed into [k][node]
                int n = tid >> 2, ch = tid & 3;
                int node = node0 + n;
                float4 vx = make_float4(0.f, 0.f, 0.f, 0.f);
                float4 va = make_float4(0.f, 0.f, 0.f, 0.f);
                if (node < N_NODES) {
                    vx = *(const float4*)(x      + (size_t)node * F + kp * 16 + ch * 4);
                    va = *(const float4*)(g_agg1 + (size_t)node * F + kp * 16 + ch * 4);
                }
                int kb = ch * 4;
                sm[SM_XP + (kb + 0) * 68 + n] = vx.x;
                sm[SM_XP + (kb + 1) * 68 + n] = vx.y;
                sm[SM_XP + (kb + 2) * 68 + n] = vx.z;
                sm[SM_XP + (kb + 3) * 68 + n] = vx.w;
                sm[SM_AP + (kb + 0) * 68 + n] = va.x;
                sm[SM_AP + (kb + 1) * 68 + n] = va.y;
                sm[SM_AP + (kb + 2) * 68 + n] = va.z;
                sm[SM_AP + (kb + 3) * 68 + n] = va.w;
            }
            __syncthreads();
#pragma unroll
            for (int k = 0; k < 16; k++) {
                float4 xv = *(float4*)&sm[SM_XP + k * 68 + ty * 4];
                float4 av = *(float4*)&sm[SM_AP + k * 68 + ty * 4];
                unsigned long long wsp0, wsp1, wnp0, wnp1;
                {
                    float4 ws = *(float4*)&sm[SM_W + (kp * 16 + k) * 64 + tx * 4];
                    float4 wn = *(float4*)&sm[SM_W + (64 + kp * 16 + k) * 64 + tx * 4];
                    wsp0 = pack2(ws.x, ws.y); wsp1 = pack2(ws.z, ws.w);
                    wnp0 = pack2(wn.x, wn.y); wnp1 = pack2(wn.z, wn.w);
                }
                unsigned long long xs[4], as_[4];
                xs[0] = pack2(xv.x, xv.x); xs[1] = pack2(xv.y, xv.y);
                xs[2] = pack2(xv.z, xv.z); xs[3] = pack2(xv.w, xv.w);
                as_[0] = pack2(av.x, av.x); as_[1] = pack2(av.y, av.y);
                as_[2] = pack2(av.z, av.z); as_[3] = pack2(av.w, av.w);
#pragma unroll
                for (int i = 0; i < 4; i++) {
                    acc[i][0] = fma2(wsp0, xs[i], acc[i][0]);
                    acc[i][0] = fma2(wnp0, as_[i], acc[i][0]);
                    acc[i][1] = fma2(wsp1, xs[i], acc[i][1]);
                    acc[i][1] = fma2(wnp1, as_[i], acc[i][1]);
                }
            }
        }
        // relu + bias -> sH
#pragma unroll
        for (int i = 0; i < 4; i++) {
            float h0, h1, h2, h3;
            unpack2(acc[i][0], h0, h1);
            unpack2(acc[i][1], h2, h3);
            float4 hv;
            hv.x = fmaxf(h0 + bb.x, 0.f);
            hv.y = fmaxf(h1 + bb.y, 0.f);
            hv.z = fmaxf(h2 + bb.z, 0.f);
            hv.w = fmaxf(h3 + bb.w, 0.f);
            *(float4*)&sm[SM_H + (ty * 4 + i) * 68 + tx * 4] = hv;
        }
        __syncthreads();
        // phase 2: p2 = h@Wn2, q2 = h@Ws2. thread: node = tid>>2, 8 of 32 cols.
        {
            int n = tid >> 2, part = tid & 3;
            unsigned long long o[4] = {0ull, 0ull, 0ull, 0ull};
#pragma unroll
            for (int k = 0; k < 64; k++) {
                float hv = sm[SM_H + n * 68 + k];
                unsigned long long hs = pack2(hv, hv);
                float4 w0 = *(float4*)&sm[SM_W2 + k * 32 + part * 8];
                float4 w1 = *(float4*)&sm[SM_W2 + k * 32 + part * 8 + 4];
                o[0] = fma2(pack2(w0.x, w0.y), hs, o[0]);
                o[1] = fma2(pack2(w0.z, w0.w), hs, o[1]);
                o[2] = fma2(pack2(w1.x, w1.y), hs, o[2]);
                o[3] = fma2(pack2(w1.z, w1.w), hs, o[3]);
            }
            int node = node0 + n;
            if (node < N_NODES) {
                float4 r0, r1;
                unpack2(o[0], r0.x, r0.y); unpack2(o[1], r0.z, r0.w);
                unpack2(o[2], r1.x, r1.y); unpack2(o[3], r1.z, r1.w);
                if (part < 2) {
                    *(float4*)(g_p2 + (size_t)node * C + part * 8)     = r0;
                    *(float4*)(g_p2 + (size_t)node * C + part * 8 + 4) = r1;
                } else {
                    *(float4*)(g_q2 + (size_t)node * C + (part - 2) * 8)     = r0;
                    *(float4*)(g_q2 + (size_t)node * C + (part - 2) * 8 + 4) = r1;
                }
            }
        }
        __syncthreads();
    }
}

// ---------------- gather2 + output: out = q2 + mean_agg(p2) + b2 --------
// 4 lanes/node (16 floats = 4 float4), 256 thr = 64 nodes/block.
__global__ void gather2_out_kernel(const float* __restrict__ b2,
                                   float* __restrict__ out) {
    int node = blockIdx.x * 64 + (threadIdx.x >> 2);
    int l = threadIdx.x & 3;
    if (node >= N_NODES) return;
    int beg = g_off[node], end = g_off[node + 1];
    float4 acc = make_float4(0.f, 0.f, 0.f, 0.f);
    int i = beg;
    for (; i + 4 <= end; i += 4) {
        int s0 = g_csr_src[i];
        int s1 = g_csr_src[i + 1];
        int s2 = g_csr_src[i + 2];
        int s3 = g_csr_src[i + 3];
        float4 a = *(const float4*)(g_p2 + (size_t)s0 * C + l * 4);
        float4 b = *(const float4*)(g_p2 + (size_t)s1 * C + l * 4);
        float4 c = *(const float4*)(g_p2 + (size_t)s2 * C + l * 4);
        float4 d = *(const float4*)(g_p2 + (size_t)s3 * C + l * 4);
        acc.x += (a.x + b.x) + (c.x + d.x);
        acc.y += (a.y + b.y) + (c.y + d.y);
        acc.z += (a.z + b.z) + (c.z + d.z);
        acc.w += (a.w + b.w) + (c.w + d.w);
    }
    for (; i < end; i++) {
        int s0 = g_csr_src[i];
        float4 a = *(const float4*)(g_p2 + (size_t)s0 * C + l * 4);
        acc.x += a.x; acc.y += a.y; acc.z += a.z; acc.w += a.w;
    }
    float inv = 1.0f / (float)max(end - beg, 1);
    float4 q = *(const float4*)(g_q2 + (size_t)node * C + l * 4);
    float4 bv = *(const float4*)(b2 + l * 4);
    float4 r;
    r.x = q.x + acc.x * inv + bv.x;
    r.y = q.y + acc.y * inv + bv.y;
    r.z = q.z + acc.z * inv + bv.z;
    r.w = q.w + acc.w * inv + bv.w;
    *(float4*)(out + (size_t)node * C + l * 4) = r;
}

// ---------------- launch ----------------
extern "C" void kernel_launch(void* const* d_in, const int* in_sizes, int n_in,
                              void* d_out, int out_size) {
    const float* x   = (const float*)d_in[0];
    const int*   src = (const int*)d_in[1];
    const int*   dst = (const int*)d_in[2];
    const float* Ws1 = (const float*)d_in[3];
    const float* Wn1 = (const float*)d_in[4];
    const float* b1  = (const float*)d_in[5];
    const float* Ws2 = (const float*)d_in[6];
    const float* Wn2 = (const float*)d_in[7];
    const float* b2  = (const float*)d_in[8];
    float* out = (float*)d_out;

    // host-side only; runs at capture time, not during replay
    cudaFuncSetAttribute(layer1_kernel,
                         cudaFuncAttributeMaxDynamicSharedMemorySize,
                         SM_TOT * (int)sizeof(float));

    detect_zero_kernel<<<(N_NODES + 255) / 256, 256>>>((const unsigned int*)src);
    convert_hist_kernel<<<(N_EDGES + 255) / 256, 256>>>(src, dst);

    scan1_kernel<<<N_BLK1, SCAN_B>>>();
    scan2_kernel<<<1, SCAN_B>>>();
    scan3_kernel<<<N_BLK1, SCAN_B>>>();
    fill_kernel<<<(N_EDGES + 255) / 256, 256>>>();

    gather1_kernel<<<(N_NODES + 15) / 16, 256>>>(x);
    layer1_kernel<<<296, 256, SM_TOT * (int)sizeof(float)>>>(x, Ws1, Wn1, b1, Wn2, Ws2);
    gather2_out_kernel<<<(N_NODES + 63) / 64, 256>>>(b2, out);
}